// round 2
// baseline (speedup 1.0000x reference)
#include <cuda_runtime.h>
#include <math.h>

// ---- problem config ----
#define BB 4
#define NN 16384
#define REG_CH 76
#define PRE 2250
#define POST 128
#define MW 71            // ceil(PRE/32)
#define NSORT 16384
#define NMS_THRESH 0.8f
#define TWO_PI_F 6.2831853071795864769f
#define PI_F 3.14159265358979323846f
#define APC_F 0.52359877559829887308f       // 2pi/12, rounds to f32
#define APC_HALF_F 0.26179938779914943654f  // pi/12

// ---- scratch (no allocations allowed) ----
__device__ int      g_top_idx[BB * PRE];
__device__ float    g_top_score[BB * PRE];
__device__ float    g_boxes[BB * PRE * 7];
__device__ float    g_bev[BB * PRE * 4];     // x1,z1,x2,z2
__device__ float    g_area[BB * PRE];
__device__ unsigned g_mask[BB * PRE * MW];

// ============================================================
// Kernel 1: per-image full bitonic sort of packed u64 keys,
// key = (descending-monotone score bits << 32) | idx, so an
// ASCENDING sort yields score-descending, index-ascending (ties),
// matching stable jnp.argsort(-scores).
// ============================================================
__global__ void sort_topk_kernel(const float* __restrict__ scores) {
    extern __shared__ unsigned long long s[];
    const int img = blockIdx.x;
    const float* sc = scores + (size_t)img * NN;

    for (int i = threadIdx.x; i < NSORT; i += blockDim.x) {
        unsigned u = __float_as_uint(sc[i]);
        // ascending-monotone map
        unsigned asc = (u & 0x80000000u) ? ~u : (u | 0x80000000u);
        unsigned desc = ~asc;   // descending-monotone
        s[i] = ((unsigned long long)desc << 32) | (unsigned)i;
    }
    __syncthreads();

    for (int k = 2; k <= NSORT; k <<= 1) {
        for (int j = k >> 1; j > 0; j >>= 1) {
            for (int i = threadIdx.x; i < NSORT; i += blockDim.x) {
                int ixj = i ^ j;
                if (ixj > i) {
                    unsigned long long a = s[i], b = s[ixj];
                    bool asc = ((i & k) == 0);
                    if ((a > b) == asc) { s[i] = b; s[ixj] = a; }
                }
            }
            __syncthreads();
        }
    }
    // ascending sort of descending keys -> top PRE at the head, in order
    for (int r = threadIdx.x; r < PRE; r += blockDim.x) {
        int idx = (int)(s[r] & 0xffffffffu);
        g_top_idx[img * PRE + r] = idx;
        g_top_score[img * PRE + r] = sc[idx];
    }
}

// ============================================================
// Kernel 2: decode selected boxes. All float ops via *_rn
// intrinsics to prevent FMA contraction (must match XLA op-wise).
// ============================================================
__global__ void decode_kernel(const float* __restrict__ reg,
                              const float* __restrict__ xyz,
                              const float* __restrict__ anchor) {
    int m = blockIdx.x * blockDim.x + threadIdx.x;
    if (m >= BB * PRE) return;
    int img = m / PRE;
    int idx = g_top_idx[m];
    const float* r = reg + (size_t)(img * NN + idx) * REG_CH;
    const float* p = xyz + (size_t)(img * NN + idx) * 3;

    // argmax bins (first max, like jnp.argmax)
    int xb = 0; float bv = r[0];
    #pragma unroll
    for (int t = 1; t < 12; t++) if (r[t] > bv) { bv = r[t]; xb = t; }
    int zb = 0; bv = r[12];
    #pragma unroll
    for (int t = 1; t < 12; t++) if (r[12 + t] > bv) { bv = r[12 + t]; zb = t; }

    // pos_x = ((xb*0.5 + 0.25) - 3.0) + res*0.5, op-by-op
    float pos_x = __fadd_rn(__fsub_rn(__fadd_rn(__fmul_rn((float)xb, 0.5f), 0.25f), 3.0f),
                            __fmul_rn(r[24 + xb], 0.5f));
    float pos_z = __fadd_rn(__fsub_rn(__fadd_rn(__fmul_rn((float)zb, 0.5f), 0.25f), 3.0f),
                            __fmul_rn(r[36 + zb], 0.5f));
    float x = __fadd_rn(pos_x, p[0]);
    float z = __fadd_rn(pos_z, p[2]);
    float y = __fadd_rn(p[1], r[48]);

    int rb = 0; bv = r[49];
    #pragma unroll
    for (int t = 1; t < 12; t++) if (r[49 + t] > bv) { bv = r[49 + t]; rb = t; }
    float ry = __fadd_rn(__fmul_rn((float)rb, APC_F),
                         __fmul_rn(r[61 + rb], APC_HALF_F));
    // jnp.remainder(ry, 2pi): fmod then sign fixup
    float rem = fmodf(ry, TWO_PI_F);
    if (rem != 0.0f && (rem < 0.0f)) rem = __fadd_rn(rem, TWO_PI_F);
    ry = rem;
    if (ry > PI_F) ry = __fsub_rn(ry, TWO_PI_F);

    float ah = anchor[0], aw = anchor[1], al = anchor[2];
    float h = __fadd_rn(__fmul_rn(r[73], ah), ah);
    float w = __fadd_rn(__fmul_rn(r[74], aw), aw);
    float l = __fadd_rn(__fmul_rn(r[75], al), al);
    y = __fadd_rn(y, __fmul_rn(h, 0.5f));

    float* bo = g_boxes + (size_t)m * 7;
    bo[0] = x; bo[1] = y; bo[2] = z; bo[3] = h; bo[4] = w; bo[5] = l; bo[6] = ry;

    float x1 = __fsub_rn(x, __fmul_rn(l, 0.5f));
    float x2 = __fadd_rn(x, __fmul_rn(l, 0.5f));
    float z1 = __fsub_rn(z, __fmul_rn(w, 0.5f));
    float z2 = __fadd_rn(z, __fmul_rn(w, 0.5f));
    float* b4 = g_bev + (size_t)m * 4;
    b4[0] = x1; b4[1] = z1; b4[2] = x2; b4[3] = z2;
    g_area[m] = __fmul_rn(__fsub_rn(x2, x1), __fsub_rn(z2, z1));
}

// ============================================================
// Kernel 3: suppression bitmask (only j > i bits matter).
// IoU computed op-by-op with *_rn intrinsics (bitwise == XLA).
// ============================================================
__global__ void mask_kernel() {
    int gid = blockIdx.x * blockDim.x + threadIdx.x;
    const int total = BB * PRE * MW;
    if (gid >= total) return;
    int w   = gid % MW;
    int i   = (gid / MW) % PRE;
    int img = gid / (MW * PRE);

    const float* bv = g_bev  + (size_t)img * PRE * 4;
    const float* ar = g_area + (size_t)img * PRE;
    float x1 = bv[i * 4 + 0], z1 = bv[i * 4 + 1];
    float x2 = bv[i * 4 + 2], z2 = bv[i * 4 + 3];
    float ai = ar[i];

    unsigned bits = 0;
    int j0 = w * 32;
    for (int b = 0; b < 32; b++) {
        int j = j0 + b;
        if (j <= i || j >= PRE) continue;
        float iw = fmaxf(__fsub_rn(fminf(x2, bv[j * 4 + 2]), fmaxf(x1, bv[j * 4 + 0])), 0.0f);
        float ih = fmaxf(__fsub_rn(fminf(z2, bv[j * 4 + 3]), fmaxf(z1, bv[j * 4 + 1])), 0.0f);
        float inter = __fmul_rn(iw, ih);
        float denom = __fsub_rn(__fadd_rn(ai, ar[j]), inter);
        float iou = __fdiv_rn(inter, denom);
        if (iou > NMS_THRESH) bits |= (1u << b);
    }
    g_mask[gid] = bits;
}

// ============================================================
// Kernel 4: warp-serial greedy NMS + gather output
// out layout: [bbox3d (B,POST,7) | scores (B,POST)] f32
// ============================================================
__global__ void nms_gather_kernel(float* __restrict__ out) {
    const int img = blockIdx.x;
    const int lane = threadIdx.x;
    __shared__ unsigned remv[MW];
    __shared__ int keep[POST];

    for (int wv = lane; wv < MW; wv += 32) remv[wv] = 0;
    __syncwarp();

    int cnt = 0;
    for (int i = 0; i < PRE && cnt < POST; i++) {
        unsigned sup = remv[i >> 5] & (1u << (i & 31));
        if (!sup) {
            if (lane == 0) keep[cnt] = i;
            const unsigned* mrow = g_mask + (size_t)(img * PRE + i) * MW;
            for (int wv = lane; wv < MW; wv += 32) remv[wv] |= mrow[wv];
            cnt++;
            __syncwarp();
        }
    }
    __syncwarp();

    float* ob = out + (size_t)img * POST * 7;
    float* os = out + (size_t)BB * POST * 7 + (size_t)img * POST;
    for (int p = lane; p < POST; p += 32) {
        if (p < cnt) {
            int i = keep[p];
            const float* bo = g_boxes + (size_t)(img * PRE + i) * 7;
            #pragma unroll
            for (int c = 0; c < 7; c++) ob[p * 7 + c] = bo[c];
            os[p] = g_top_score[img * PRE + i];
        } else {
            #pragma unroll
            for (int c = 0; c < 7; c++) ob[p * 7 + c] = 0.0f;
            os[p] = 0.0f;
        }
    }
}

// ============================================================
extern "C" void kernel_launch(void* const* d_in, const int* in_sizes, int n_in,
                              void* d_out, int out_size) {
    const float* scores = (const float*)d_in[0];   // (B,N)
    const float* reg    = (const float*)d_in[1];   // (B,N,76)
    const float* xyz    = (const float*)d_in[2];   // (B,N,3)
    const float* anchor = (const float*)d_in[3];   // (3,)
    float* out = (float*)d_out;

    static bool attr_set = false;
    if (!attr_set) {
        cudaFuncSetAttribute(sort_topk_kernel,
                             cudaFuncAttributeMaxDynamicSharedMemorySize,
                             NSORT * sizeof(unsigned long long));
        attr_set = true;
    }

    sort_topk_kernel<<<BB, 1024, NSORT * sizeof(unsigned long long)>>>(scores);

    {
        int total = BB * PRE;
        decode_kernel<<<(total + 127) / 128, 128>>>(reg, xyz, anchor);
    }
    {
        int total = BB * PRE * MW;
        mask_kernel<<<(total + 127) / 128, 128>>>();
    }
    nms_gather_kernel<<<BB, 32>>>(out);
}

// round 3
// speedup vs baseline: 2.1444x; 2.1444x over previous
#include <cuda_runtime.h>
#include <math.h>

// ---- problem config ----
#define BB 4
#define NN 16384
#define REG_CH 76
#define PRE 2250
#define POST 128
#define NSORT 16384
#define CAND 4096
#define NMS_THRESH 0.8f
#define TWO_PI_F 6.2831853071795864769f
#define PI_F 3.14159265358979323846f
#define APC_F 0.52359877559829887308f       // 2pi/12
#define APC_HALF_F 0.26179938779914943654f  // pi/12

// ---- scratch ----
__device__ int   g_top_idx[BB * PRE];
__device__ float g_top_score[BB * PRE];
__device__ float g_boxes[BB * PRE * 7];
__device__ float g_bev[BB * PRE * 4];     // x1,z1,x2,z2
__device__ float g_area[BB * PRE];

__device__ __forceinline__ unsigned desc_key(float f) {
    unsigned u = __float_as_uint(f);
    unsigned asc = (u & 0x80000000u) ? ~u : (u | 0x80000000u);
    return ~asc;   // ascending key order == descending score order
}

// bitonic sort of a[0..n) (n power of 2) in smem, ascending u64
__device__ __forceinline__ void bitonic_sort(unsigned long long* a, int n,
                                             int tid, int nthreads) {
    for (int k = 2; k <= n; k <<= 1) {
        for (int j = k >> 1; j > 0; j >>= 1) {
            for (int i = tid; i < n; i += nthreads) {
                int ixj = i ^ j;
                if (ixj > i) {
                    unsigned long long x = a[i], y = a[ixj];
                    bool asc = ((i & k) == 0);
                    if ((x > y) == asc) { a[i] = y; a[ixj] = x; }
                }
            }
            __syncthreads();
        }
    }
}

// ============================================================
// Kernel 1: per-image top-PRE via radix-select + 4K bitonic sort.
// Fallback: full 16K bitonic sort if candidate count > CAND.
// Dynamic smem = 128KB (full-sort capacity).
// ============================================================
__global__ void topk_kernel(const float* __restrict__ scores) {
    extern __shared__ char sm[];
    unsigned* hist = (unsigned*)sm;                        // 4096 u32 = 16KB
    unsigned long long* cand = (unsigned long long*)(sm + 16384); // 4096 u64 = 32KB
    __shared__ unsigned wsum[32];
    __shared__ int sT;
    __shared__ int sCnt;

    const int img = blockIdx.x;
    const int tid = threadIdx.x;
    const int lane = tid & 31;
    const int wid = tid >> 5;
    const float* sc = scores + (size_t)img * NN;

    // --- histogram on top 12 bits of desc key ---
    for (int b = tid; b < 4096; b += 1024) hist[b] = 0;
    if (tid == 0) { sT = 4096; sCnt = 0; }
    __syncthreads();
    for (int i = tid; i < NN; i += 1024) {
        unsigned k = desc_key(sc[i]);
        atomicAdd(&hist[k >> 20], 1u);
    }
    __syncthreads();

    // --- blocked inclusive prefix scan of hist[4096] (4 per thread) ---
    int b0 = tid * 4;
    unsigned v0 = hist[b0], v1 = hist[b0 + 1], v2 = hist[b0 + 2], v3 = hist[b0 + 3];
    unsigned i1 = v0 + v1, i2 = i1 + v2, i3 = i2 + v3;
    unsigned x = i3;
    #pragma unroll
    for (int d = 1; d < 32; d <<= 1) {
        unsigned y = __shfl_up_sync(0xffffffffu, x, d);
        if (lane >= d) x += y;
    }
    if (lane == 31) wsum[wid] = x;
    __syncthreads();
    if (wid == 0) {
        unsigned w = wsum[lane];
        #pragma unroll
        for (int d = 1; d < 32; d <<= 1) {
            unsigned y = __shfl_up_sync(0xffffffffu, w, d);
            if (lane >= d) w += y;
        }
        wsum[lane] = w;
    }
    __syncthreads();
    unsigned excl = ((wid > 0) ? wsum[wid - 1] : 0u) + (x - i3);
    hist[b0]     = excl + v0;
    hist[b0 + 1] = excl + i1;
    hist[b0 + 2] = excl + i2;
    hist[b0 + 3] = excl + i3;
    __syncthreads();

    // --- threshold bucket: min b with cum[b] >= PRE ---
    #pragma unroll
    for (int k = 0; k < 4; k++)
        if (hist[b0 + k] >= PRE) atomicMin(&sT, b0 + k);
    __syncthreads();
    const unsigned T = (unsigned)sT;
    const int C = (int)hist[T];     // candidate count
    __syncthreads();                // all reads of hist done before any reuse

    if (C <= CAND) {
        // --- compact candidates (bucket <= T) ---
        for (int i = tid; i < NN; i += 1024) {
            unsigned k = desc_key(sc[i]);
            if ((k >> 20) <= T) {
                int pos = atomicAdd(&sCnt, 1);
                cand[pos] = ((unsigned long long)k << 32) | (unsigned)i;
            }
        }
        __syncthreads();
        for (int p = C + tid; p < CAND; p += 1024)
            cand[p] = 0xffffffffffffffffull;
        __syncthreads();

        bitonic_sort(cand, CAND, tid, 1024);

        for (int r = tid; r < PRE; r += 1024) {
            int idx = (int)(cand[r] & 0xffffffffu);
            g_top_idx[img * PRE + r] = idx;
            g_top_score[img * PRE + r] = sc[idx];
        }
    } else {
        // --- fallback: full 16K sort ---
        unsigned long long* s = (unsigned long long*)sm;
        for (int i = tid; i < NSORT; i += 1024)
            s[i] = ((unsigned long long)desc_key(sc[i]) << 32) | (unsigned)i;
        __syncthreads();
        bitonic_sort(s, NSORT, tid, 1024);
        for (int r = tid; r < PRE; r += 1024) {
            int idx = (int)(s[r] & 0xffffffffu);
            g_top_idx[img * PRE + r] = idx;
            g_top_score[img * PRE + r] = sc[idx];
        }
    }
}

// ============================================================
// Kernel 2: decode selected boxes (all ops *_rn, matches XLA)
// ============================================================
__global__ void decode_kernel(const float* __restrict__ reg,
                              const float* __restrict__ xyz,
                              const float* __restrict__ anchor) {
    int m = blockIdx.x * blockDim.x + threadIdx.x;
    if (m >= BB * PRE) return;
    int img = m / PRE;
    int idx = g_top_idx[m];
    const float* r = reg + (size_t)(img * NN + idx) * REG_CH;
    const float* p = xyz + (size_t)(img * NN + idx) * 3;

    int xb = 0; float bv = r[0];
    #pragma unroll
    for (int t = 1; t < 12; t++) if (r[t] > bv) { bv = r[t]; xb = t; }
    int zb = 0; bv = r[12];
    #pragma unroll
    for (int t = 1; t < 12; t++) if (r[12 + t] > bv) { bv = r[12 + t]; zb = t; }

    float pos_x = __fadd_rn(__fsub_rn(__fadd_rn(__fmul_rn((float)xb, 0.5f), 0.25f), 3.0f),
                            __fmul_rn(r[24 + xb], 0.5f));
    float pos_z = __fadd_rn(__fsub_rn(__fadd_rn(__fmul_rn((float)zb, 0.5f), 0.25f), 3.0f),
                            __fmul_rn(r[36 + zb], 0.5f));
    float x = __fadd_rn(pos_x, p[0]);
    float z = __fadd_rn(pos_z, p[2]);
    float y = __fadd_rn(p[1], r[48]);

    int rb = 0; bv = r[49];
    #pragma unroll
    for (int t = 1; t < 12; t++) if (r[49 + t] > bv) { bv = r[49 + t]; rb = t; }
    float ry = __fadd_rn(__fmul_rn((float)rb, APC_F),
                         __fmul_rn(r[61 + rb], APC_HALF_F));
    float rem = fmodf(ry, TWO_PI_F);
    if (rem != 0.0f && rem < 0.0f) rem = __fadd_rn(rem, TWO_PI_F);
    ry = rem;
    if (ry > PI_F) ry = __fsub_rn(ry, TWO_PI_F);

    float ah = anchor[0], aw = anchor[1], al = anchor[2];
    float h = __fadd_rn(__fmul_rn(r[73], ah), ah);
    float w = __fadd_rn(__fmul_rn(r[74], aw), aw);
    float l = __fadd_rn(__fmul_rn(r[75], al), al);
    y = __fadd_rn(y, __fmul_rn(h, 0.5f));

    float* bo = g_boxes + (size_t)m * 7;
    bo[0] = x; bo[1] = y; bo[2] = z; bo[3] = h; bo[4] = w; bo[5] = l; bo[6] = ry;

    float x1 = __fsub_rn(x, __fmul_rn(l, 0.5f));
    float x2 = __fadd_rn(x, __fmul_rn(l, 0.5f));
    float z1 = __fsub_rn(z, __fmul_rn(w, 0.5f));
    float z2 = __fadd_rn(z, __fmul_rn(w, 0.5f));
    float* b4 = g_bev + (size_t)m * 4;
    b4[0] = x1; b4[1] = z1; b4[2] = x2; b4[3] = z2;
    g_area[m] = __fmul_rn(__fsub_rn(x2, x1), __fsub_rn(z2, z1));
}

// ============================================================
// Kernel 3: fused greedy NMS (IoU on demand, smem-resident) + gather
// One block per image, 512 threads. out: [bbox3d (B,POST,7) | scores]
// ============================================================
#define NMS_T 512
__global__ void nms_fused_kernel(float* __restrict__ out) {
    __shared__ float sx1[PRE], sz1[PRE], sx2[PRE], sz2[PRE], sar[PRE]; // 45000B
    __shared__ int keep[POST];                                         // 512B
    __shared__ unsigned char sup[PRE];                                 // 2250B

    const int img = blockIdx.x;
    const int tid = threadIdx.x;

    for (int m = tid; m < PRE; m += NMS_T) {
        const float* b4 = g_bev + (size_t)(img * PRE + m) * 4;
        sx1[m] = b4[0]; sz1[m] = b4[1]; sx2[m] = b4[2]; sz2[m] = b4[3];
        sar[m] = g_area[img * PRE + m];
        sup[m] = 0;
    }
    __syncthreads();

    int cnt = 0;
    for (int i = 0; i < PRE; i++) {
        if (sup[i]) continue;           // uniform read; suppressed rows write nothing
        if (tid == 0) keep[cnt] = i;
        float x1 = sx1[i], z1 = sz1[i], x2 = sx2[i], z2 = sz2[i], ai = sar[i];
        for (int j = tid; j < PRE; j += NMS_T) {
            if (j > i) {
                float iw = fmaxf(__fsub_rn(fminf(x2, sx2[j]), fmaxf(x1, sx1[j])), 0.0f);
                float ih = fmaxf(__fsub_rn(fminf(z2, sz2[j]), fmaxf(z1, sz1[j])), 0.0f);
                float inter = __fmul_rn(iw, ih);
                float denom = __fsub_rn(__fadd_rn(ai, sar[j]), inter);
                float iou = __fdiv_rn(inter, denom);
                if (iou > NMS_THRESH) sup[j] = 1;
            }
        }
        __syncthreads();
        cnt++;
        if (cnt == POST) break;
    }
    __syncthreads();

    float* ob = out + (size_t)img * POST * 7;
    float* os = out + (size_t)BB * POST * 7 + (size_t)img * POST;
    for (int p = tid; p < POST; p += NMS_T) {
        if (p < cnt) {
            int i = keep[p];
            const float* bo = g_boxes + (size_t)(img * PRE + i) * 7;
            #pragma unroll
            for (int c = 0; c < 7; c++) ob[p * 7 + c] = bo[c];
            os[p] = g_top_score[img * PRE + i];
        } else {
            #pragma unroll
            for (int c = 0; c < 7; c++) ob[p * 7 + c] = 0.0f;
            os[p] = 0.0f;
        }
    }
}

// ============================================================
extern "C" void kernel_launch(void* const* d_in, const int* in_sizes, int n_in,
                              void* d_out, int out_size) {
    const float* scores = (const float*)d_in[0];   // (B,N)
    const float* reg    = (const float*)d_in[1];   // (B,N,76)
    const float* xyz    = (const float*)d_in[2];   // (B,N,3)
    const float* anchor = (const float*)d_in[3];   // (3,)
    float* out = (float*)d_out;

    static bool attr_set = false;
    if (!attr_set) {
        cudaFuncSetAttribute(topk_kernel,
                             cudaFuncAttributeMaxDynamicSharedMemorySize,
                             NSORT * sizeof(unsigned long long));
        attr_set = true;
    }

    topk_kernel<<<BB, 1024, NSORT * sizeof(unsigned long long)>>>(scores);
    {
        int total = BB * PRE;
        decode_kernel<<<(total + 127) / 128, 128>>>(reg, xyz, anchor);
    }
    nms_fused_kernel<<<BB, NMS_T>>>(out);
}